// round 9
// baseline (speedup 1.0000x reference)
#include <cuda_runtime.h>
#include <cstdint>

#define DIMX 32
#define NB   6
#define BB   16
#define NN   256
#define XPD  16
#define TPD  8

#define TOTAL   (BB * NN * NN)       // 1,048,576 pairs
#define TPB     384
#define GRID    ((TOTAL + TPB - 1) / TPB)   // 2731

typedef unsigned long long u64;

__device__ __align__(16) float g_cf[BB * NB * DIMX];
__device__ __align__(16) float g_cg[BB * NB * DIMX];

// Weights in constant memory (warp-uniform -> LDCU on the uniform/const port,
// off the L1TEX/LSU path). 5120+5120+5120 floats = 60 KB < 64 KB limit.
__constant__ __align__(16) float c_fWh[5 * 1024];   // f_Wh[1..5]
__constant__ __align__(16) float c_gWh[5 * 1024];   // g_Wh[1..5]
__constant__ __align__(16) float c_gWz[5 * 1024];   // g_Wz[1..5] rows 0..31

// ---------------- packed f32x2 helpers ----------------
__device__ __forceinline__ u64 ffma2(u64 a, u64 b, u64 c) {
    u64 d;
    asm("fma.rn.f32x2 %0, %1, %2, %3;" : "=l"(d) : "l"(a), "l"(b), "l"(c));
    return d;
}
__device__ __forceinline__ u64 pack2(float v) {
    u64 r;
    asm("mov.b64 %0, {%1, %1};" : "=l"(r) : "f"(v));
    return r;
}
__device__ __forceinline__ float2 unpack2(u64 v) {
    float lo, hi;
    asm("mov.b64 {%0, %1}, %2;" : "=f"(lo), "=f"(hi) : "l"(v));
    return make_float2(lo, hi);
}

// ---------------- precompute: embeddings + folded constants ----------------
__global__ void precompute_kernel(
    const float* __restrict__ x_params, const float* __restrict__ t_params,
    const float* __restrict__ xW1, const float* __restrict__ xb1,
    const float* __restrict__ xW2, const float* __restrict__ xb2,
    const float* __restrict__ tW1, const float* __restrict__ tb1,
    const float* __restrict__ tW2, const float* __restrict__ tb2,
    const float* __restrict__ f_bh, const float* __restrict__ f_Wz, const float* __restrict__ f_bz,
    const float* __restrict__ g_bh, const float* __restrict__ g_Wz, const float* __restrict__ g_bz,
    const float* __restrict__ h0,   const float* __restrict__ gh0,
    const float* __restrict__ f_Wh, const float* __restrict__ g_Wh)
{
    int b = blockIdx.x;
    int d = threadIdx.x;  // 0..31
    __shared__ float hid[DIMX], ex_s[DIMX], et_s[DIMX];

    float a = xb1[d];
    #pragma unroll
    for (int m = 0; m < XPD; m++) a += x_params[b * XPD + m] * xW1[m * DIMX + d];
    hid[d] = sinf(a);
    __syncthreads();
    float e = xb2[d];
    #pragma unroll
    for (int m = 0; m < DIMX; m++) e += hid[m] * xW2[m * DIMX + d];
    ex_s[d] = e;
    __syncthreads();

    a = tb1[d];
    #pragma unroll
    for (int m = 0; m < TPD; m++) a += t_params[b * TPD + m] * tW1[m * DIMX + d];
    hid[d] = sinf(a);
    __syncthreads();
    e = tb2[d];
    #pragma unroll
    for (int m = 0; m < DIMX; m++) e += hid[m] * tW2[m * DIMX + d];
    et_s[d] = e;
    __syncthreads();

    for (int k = 0; k < NB; k++) {
        float cf = f_bh[k * DIMX + d] + f_bz[k * DIMX + d];
        const float* Wz = f_Wz + k * 34 * DIMX;
        #pragma unroll
        for (int m = 0; m < DIMX; m++) cf += et_s[m] * Wz[(2 + m) * DIMX + d];
        if (k == 0) {
            #pragma unroll
            for (int m = 0; m < DIMX; m++) cf += h0[m] * f_Wh[m * DIMX + d];
        }
        g_cf[(b * NB + k) * DIMX + d] = cf;

        float cg = g_bh[k * DIMX + d] + g_bz[k * DIMX + d];
        const float* gWz = g_Wz + k * 64 * DIMX;
        #pragma unroll
        for (int m = 0; m < DIMX; m++) cg += ex_s[m] * gWz[(32 + m) * DIMX + d];
        if (k == 0) {
            #pragma unroll
            for (int m = 0; m < DIMX; m++) cg += gh0[m] * g_Wh[m * DIMX + d];
        }
        g_cg[(b * NB + k) * DIMX + d] = cg;
    }
}

// ---------------- main kernel: 1 pair/thread, weights in constant ----------------
// smem: wzx 192 | wzt 192 | dW 32 | dB 1(+pad 7) | gWz0 1024  = 1448 floats
#define OFF_WZX 0
#define OFF_WZT 192
#define OFF_DW  384
#define OFF_DB  416
#define OFF_GWZ0 424
#define SMEM_FLOATS 1448
#define SMEM_BYTES  (SMEM_FLOATS * 4)

extern __shared__ float smem[];

__global__ void __launch_bounds__(TPB, 1) pde_kernel(
    const float* __restrict__ coords,
    const float* __restrict__ g_Wz,
    const float* __restrict__ f_Wz,
    const float* __restrict__ dW,
    const float* __restrict__ dB,
    float* __restrict__ out)
{
    const int tid = threadIdx.x;

    // ---- tiny cooperative staging ----
    for (int q = tid; q < 256; q += TPB)   // g_Wz[0] rows 0..31 (1024 floats)
        ((float4*)(smem + OFF_GWZ0))[q] = ((const float4*)g_Wz)[q];
    if (tid < 192) {
        int k = tid >> 5, d = tid & 31;
        smem[OFF_WZX + tid] = f_Wz[k * 34 * DIMX + d];
        smem[OFF_WZT + tid] = f_Wz[k * 34 * DIMX + DIMX + d];
    }
    if (tid < 32) smem[OFF_DW + tid] = dW[tid];
    if (tid == 0) smem[OFF_DB] = dB[0];
    __syncthreads();

    int p = blockIdx.x * TPB + tid;
    const bool valid = (p < TOTAL);
    if (!valid) p = TOTAL - 1;
    const int b = p >> 16;
    const int i = (p >> 8) & 255;
    const int j = p & 255;

    const float x = coords[(b * NN + j) * 2 + 0];
    const float t = coords[(b * NN + i) * 2 + 1];
    const u64 xx = pack2(x);
    const u64 tt = pack2(t);

    const float* cfb = g_cf + b * (NB * DIMX);
    const float* cgb = g_cg + b * (NB * DIMX);

    float h[DIMX];

    // ---- f layer 0 (h0@Wh0 folded into cf0) ----
    {
        const float4* wx4 = (const float4*)(smem + OFF_WZX);
        const float4* wt4 = (const float4*)(smem + OFF_WZT);
        const float4* cf4 = (const float4*)(cfb);
        #pragma unroll
        for (int q = 0; q < 8; q++) {
            float4 a = wx4[q], bq = wt4[q], c = cf4[q];
            h[4*q+0] = __sinf(fmaf(x, a.x, fmaf(t, bq.x, c.x)));
            h[4*q+1] = __sinf(fmaf(x, a.y, fmaf(t, bq.y, c.y)));
            h[4*q+2] = __sinf(fmaf(x, a.z, fmaf(t, bq.z, c.z)));
            h[4*q+3] = __sinf(fmaf(x, a.w, fmaf(t, bq.w, c.w)));
        }
    }

    // ---- f layers 1..5: weights from __constant__ (uniform port) ----
    #pragma unroll 1
    for (int k = 1; k < 6; k++) {
        u64 acc[16];
        {
            const ulonglong2* c4 = (const ulonglong2*)(cfb + k * 32);
            const ulonglong2* wx = (const ulonglong2*)(smem + OFF_WZX + k * 32);
            const ulonglong2* wt = (const ulonglong2*)(smem + OFF_WZT + k * 32);
            #pragma unroll
            for (int q = 0; q < 8; q++) {
                ulonglong2 c = c4[q], a = wx[q], bt = wt[q];
                acc[2*q]   = ffma2(xx, a.x, ffma2(tt, bt.x, c.x));
                acc[2*q+1] = ffma2(xx, a.y, ffma2(tt, bt.y, c.y));
            }
        }
        const ulonglong2* W = (const ulonglong2*)(c_fWh + (k - 1) * 1024);
        #pragma unroll
        for (int kk = 0; kk < 32; kk++) {
            u64 hv = pack2(h[kk]);
            #pragma unroll
            for (int q = 0; q < 8; q++) {
                ulonglong2 w = W[kk * 8 + q];
                acc[2*q]   = ffma2(hv, w.x, acc[2*q]);
                acc[2*q+1] = ffma2(hv, w.y, acc[2*q+1]);
            }
        }
        #pragma unroll
        for (int q = 0; q < 16; q++) {
            float2 r = unpack2(acc[q]);
            h[2*q]   = __sinf(r.x);
            h[2*q+1] = __sinf(r.y);
        }
    }

    // ---- g layer 0: gh = sin(h @ gWz0 + cg0) (gWz0 from smem) ----
    float gh[DIMX];
    {
        u64 acc[16];
        {
            const ulonglong2* c4 = (const ulonglong2*)(cgb);
            #pragma unroll
            for (int q = 0; q < 8; q++) {
                ulonglong2 c = c4[q];
                acc[2*q] = c.x; acc[2*q+1] = c.y;
            }
        }
        const ulonglong2* W = (const ulonglong2*)(smem + OFF_GWZ0);
        #pragma unroll
        for (int kk = 0; kk < 32; kk++) {
            u64 hv = pack2(h[kk]);
            #pragma unroll
            for (int q = 0; q < 8; q++) {
                ulonglong2 w = W[kk * 8 + q];
                acc[2*q]   = ffma2(hv, w.x, acc[2*q]);
                acc[2*q+1] = ffma2(hv, w.y, acc[2*q+1]);
            }
        }
        #pragma unroll
        for (int q = 0; q < 16; q++) {
            float2 r = unpack2(acc[q]);
            gh[2*q]   = __sinf(r.x);
            gh[2*q+1] = __sinf(r.y);
        }
    }

    // ---- g layers 1..5: gh & h both in regs; weights from constant ----
    float u = smem[OFF_DB];
    #pragma unroll 1
    for (int k = 1; k < 6; k++) {
        u64 acc[16];
        {
            const ulonglong2* c4 = (const ulonglong2*)(cgb + k * 32);
            #pragma unroll
            for (int q = 0; q < 8; q++) {
                ulonglong2 c = c4[q];
                acc[2*q] = c.x; acc[2*q+1] = c.y;
            }
        }
        const ulonglong2* Wh = (const ulonglong2*)(c_gWh + (k - 1) * 1024);
        const ulonglong2* Wz = (const ulonglong2*)(c_gWz + (k - 1) * 1024);
        #pragma unroll
        for (int kk = 0; kk < 32; kk++) {
            u64 gv = pack2(gh[kk]);
            u64 hv = pack2(h[kk]);
            #pragma unroll
            for (int q = 0; q < 8; q++) {
                ulonglong2 wh = Wh[kk * 8 + q];
                ulonglong2 wz = Wz[kk * 8 + q];
                acc[2*q]   = ffma2(gv, wh.x, acc[2*q]);
                acc[2*q]   = ffma2(hv, wz.x, acc[2*q]);
                acc[2*q+1] = ffma2(gv, wh.y, acc[2*q+1]);
                acc[2*q+1] = ffma2(hv, wz.y, acc[2*q+1]);
            }
        }
        if (k < 5) {
            #pragma unroll
            for (int q = 0; q < 16; q++) {
                float2 r = unpack2(acc[q]);
                gh[2*q]   = __sinf(r.x);
                gh[2*q+1] = __sinf(r.y);
            }
        } else {
            const float* dw = smem + OFF_DW;
            #pragma unroll
            for (int q = 0; q < 16; q++) {
                float2 r = unpack2(acc[q]);
                u = fmaf(__sinf(r.x), dw[2*q],   u);
                u = fmaf(__sinf(r.y), dw[2*q+1], u);
            }
        }
    }

    if (valid) out[p] = u;
}

extern "C" void kernel_launch(void* const* d_in, const int* in_sizes, int n_in,
                              void* d_out, int out_size) {
    const float* coords   = (const float*)d_in[0];
    const float* x_params = (const float*)d_in[1];
    const float* t_params = (const float*)d_in[2];
    const float* xW1 = (const float*)d_in[3];
    const float* xb1 = (const float*)d_in[4];
    const float* xW2 = (const float*)d_in[5];
    const float* xb2 = (const float*)d_in[6];
    const float* tW1 = (const float*)d_in[7];
    const float* tb1 = (const float*)d_in[8];
    const float* tW2 = (const float*)d_in[9];
    const float* tb2 = (const float*)d_in[10];
    const float* h0  = (const float*)d_in[11];
    const float* gh0 = (const float*)d_in[12];
    const float* f_Wh = (const float*)d_in[13];
    const float* f_bh = (const float*)d_in[14];
    const float* f_Wz = (const float*)d_in[15];
    const float* f_bz = (const float*)d_in[16];
    const float* g_Wh = (const float*)d_in[17];
    const float* g_bh = (const float*)d_in[18];
    const float* g_Wz = (const float*)d_in[19];
    const float* g_bz = (const float*)d_in[20];
    const float* dW   = (const float*)d_in[21];
    const float* dB   = (const float*)d_in[22];

    // D2D copies into constant memory (graph-capturable, no allocation)
    cudaMemcpyToSymbolAsync(c_fWh, f_Wh + 1024, 5 * 1024 * sizeof(float), 0,
                            cudaMemcpyDeviceToDevice);
    cudaMemcpyToSymbolAsync(c_gWh, g_Wh + 1024, 5 * 1024 * sizeof(float), 0,
                            cudaMemcpyDeviceToDevice);
    for (int k = 1; k < 6; k++) {   // g_Wz[k] rows 0..31 (first 1024 floats of 2048)
        cudaMemcpyToSymbolAsync(c_gWz, g_Wz + k * 2048, 1024 * sizeof(float),
                                (k - 1) * 1024 * sizeof(float),
                                cudaMemcpyDeviceToDevice);
    }

    precompute_kernel<<<BB, 32>>>(x_params, t_params, xW1, xb1, xW2, xb2,
                                  tW1, tb1, tW2, tb2,
                                  f_bh, f_Wz, f_bz, g_bh, g_Wz, g_bz,
                                  h0, gh0, f_Wh, g_Wh);

    pde_kernel<<<GRID, TPB, SMEM_BYTES>>>(coords, g_Wz, f_Wz,
                                          dW, dB, (float*)d_out);
}